// round 8
// baseline (speedup 1.0000x reference)
#include <cuda_runtime.h>
#include <cuda_bf16.h>

#define BB 512
#define TT 512
#define LL 64
#define NTHR 128                     // tid = 2*j + h
#define NCTA (BB / 2)                // 2 batches per CTA
#define PST 68                       // padded p row: 64 + 4

__device__ float g_res[BB];
__device__ unsigned int g_done = 0;  // last-CTA ticket (self-resetting)

__global__ void __launch_bounds__(NTHR) crf_main_kernel(
    const float* __restrict__ emission,   // [B,T,L]
    const int*   __restrict__ target,     // [B,T]
    const float* __restrict__ mask,       // [B,T]
    const float* __restrict__ start_trans,// [L]
    const float* __restrict__ trans,      // [L,L]
    const float* __restrict__ end_trans,  // [L]
    float* __restrict__ out)
{
    __shared__ __align__(16) float4 sm_me[TT];        // (m0,e0,m1,e1)
    __shared__ __align__(16) float sm_p[2][2][PST];   // [buf][batch][padded 64]
    __shared__ float2 sm_s0[2];                       // (S_b0, S_b1)
    __shared__ float sm_w[4], sm_w2[4], sm_w3[4], sm_w4[4];
    __shared__ unsigned int sm_last;

    const int tid  = threadIdx.x;
    const int j    = tid >> 1;        // label 0..63
    const int h    = tid & 1;         // i-half of the dot
    const int lane = tid & 31;
    const int wid  = tid >> 5;
    const int jidx = j + ((j >> 5) << 2);   // padded p index

    const int b0 = blockIdx.x * 2;
    const int b1 = b0 + 1;
    const float* embA = emission + (size_t)b0 * TT * LL;
    const float* embB = emission + (size_t)b1 * TT * LL;
    const float* mrA  = mask + (size_t)b0 * TT;
    const float* mrB  = mask + (size_t)b1 * TT;

    // stage (mask, endmask) for both batches
    for (int t = tid; t < TT; t += NTHR) {
        float mA  = mrA[t];
        float mB  = mrB[t];
        float nmA = (t + 1 < TT) ? mrA[t + 1] : 0.0f;
        float nmB = (t + 1 < TT) ? mrB[t + 1] : 0.0f;
        sm_me[t] = make_float4(mA, (mA > nmA) ? 1.0f : 0.0f,
                               mB, (mB > nmB) ? 1.0f : 0.0f);
    }

    // E half-column (shared by both batches)
    float E[32];
    #pragma unroll
    for (int i = 0; i < 32; i++)
        E[i] = __expf(trans[(32 * h + i) * LL + j]);
    __syncthreads();

    // ---------------- path scores (both batches) ----------------
    float pA = 0.0f, pB = 0.0f;
    {
        const int* tgA = target + (size_t)b0 * TT;
        const int* tgB = target + (size_t)b1 * TT;
        for (int t = 1 + tid; t < TT; t += NTHR) {
            const float4 me = sm_me[t];
            const int tpA = tgA[t - 1], tcA = tgA[t];
            const int tpB = tgB[t - 1], tcB = tgB[t];
            pA += me.x * (trans[tpA * LL + tcA] + embA[(size_t)t * LL + tcA])
                + me.y * end_trans[tcA];
            pB += me.z * (trans[tpB * LL + tcB] + embB[(size_t)t * LL + tcB])
                + me.w * end_trans[tcB];
        }
        if (tid == 0) {
            pA += start_trans[tgA[0]] + embA[tgA[0]];
            pB += start_trans[tgB[0]] + embB[tgB[0]];
        }
        #pragma unroll
        for (int o = 16; o; o >>= 1) {
            pA += __shfl_xor_sync(0xffffffffu, pA, o);
            pB += __shfl_xor_sync(0xffffffffu, pB, o);
        }
        if (lane == 0) { sm_w[wid] = pA; sm_w2[wid] = pB; }
        __syncthreads();
    }
    const float pathA = (sm_w[0] + sm_w[1]) + (sm_w[2] + sm_w[3]);
    const float pathB = (sm_w2[0] + sm_w2[1]) + (sm_w2[2] + sm_w2[3]);

    // ---------------- forward recursions (2 independent chains) ------------
    const float et = end_trans[j];
    float sA = start_trans[j] + embA[j];
    float sB = start_trans[j] + embB[j];

    if (tid == 0) sm_s0[1] = make_float2(sA, sB);
    __syncthreads();
    float SA = sm_s0[1].x, SB = sm_s0[1].y;

    float eA1 = embA[LL + j],     eB1 = embB[LL + j];
    float eA2 = embA[2 * LL + j], eB2 = embB[2 * LL + j];

    for (int t = 1; t < TT; t++) {
        const int buf = t & 1;
        const float ecA = eA1, ecB = eB1;
        eA1 = eA2; eB1 = eB2;
        if (t + 2 < TT) {
            eA2 = embA[(size_t)(t + 2) * LL + j];
            eB2 = embB[(size_t)(t + 2) * LL + j];
        }

        if (tid == 0) sm_s0[buf] = make_float2(sA, sB);
        const float prA = __expf(sA - SA);
        const float prB = __expf(sB - SB);
        if (h == 0) {
            sm_p[buf][0][jidx] = prA;
            sm_p[buf][1][jidx] = prB;
        }
        __syncthreads();

        // half-dots for both batches, interleaved (independent chains)
        const float4* qA = (const float4*)sm_p[buf][0] + 9 * h;
        const float4* qB = (const float4*)sm_p[buf][1] + 9 * h;
        float a0 = 0.f, a1 = 0.f, a2 = 0.f, a3 = 0.f;
        float a4 = 0.f, a5 = 0.f, a6 = 0.f, a7 = 0.f;
        float c0 = 0.f, c1 = 0.f, c2 = 0.f, c3 = 0.f;
        float c4 = 0.f, c5 = 0.f, c6 = 0.f, c7 = 0.f;
        #pragma unroll
        for (int k = 0; k < 4; k++) {
            const float4 vA0 = qA[2 * k];
            const float4 vA1 = qA[2 * k + 1];
            const float4 vB0 = qB[2 * k];
            const float4 vB1 = qB[2 * k + 1];
            a0 += vA0.x * E[8 * k + 0];  c0 += vB0.x * E[8 * k + 0];
            a1 += vA0.y * E[8 * k + 1];  c1 += vB0.y * E[8 * k + 1];
            a2 += vA0.z * E[8 * k + 2];  c2 += vB0.z * E[8 * k + 2];
            a3 += vA0.w * E[8 * k + 3];  c3 += vB0.w * E[8 * k + 3];
            a4 += vA1.x * E[8 * k + 4];  c4 += vB1.x * E[8 * k + 4];
            a5 += vA1.y * E[8 * k + 5];  c5 += vB1.y * E[8 * k + 5];
            a6 += vA1.z * E[8 * k + 6];  c6 += vB1.z * E[8 * k + 6];
            a7 += vA1.w * E[8 * k + 7];  c7 += vB1.w * E[8 * k + 7];
        }
        float parA = ((a0 + a1) + (a2 + a3)) + ((a4 + a5) + (a6 + a7));
        float parB = ((c0 + c1) + (c2 + c3)) + ((c4 + c5) + (c6 + c7));
        const float dotA = parA + __shfl_xor_sync(0xffffffffu, parA, 1);
        const float dotB = parB + __shfl_xor_sync(0xffffffffu, parB, 1);

        const float4 me = sm_me[t];
        const float nxtA = SA + __logf(dotA) + ecA;
        const float nxtB = SB + __logf(dotB) + ecB;
        sA = me.x * nxtA + (1.0f - me.x) * sA + me.y * et;
        sB = me.z * nxtB + (1.0f - me.z) * sB + me.w * et;

        const float2 Sv = sm_s0[buf];
        SA = Sv.x; SB = Sv.y;
    }

    // normalizers (each label counted twice -> *0.5 inside the log)
    float wmA = sA, wmB = sB;
    #pragma unroll
    for (int o = 16; o; o >>= 1) {
        wmA = fmaxf(wmA, __shfl_xor_sync(0xffffffffu, wmA, o));
        wmB = fmaxf(wmB, __shfl_xor_sync(0xffffffffu, wmB, o));
    }
    if (lane == 0) { sm_w[wid] = wmA; sm_w2[wid] = wmB; }
    __syncthreads();
    const float MA = fmaxf(fmaxf(sm_w[0], sm_w[1]),  fmaxf(sm_w[2], sm_w[3]));
    const float MB = fmaxf(fmaxf(sm_w2[0], sm_w2[1]), fmaxf(sm_w2[2], sm_w2[3]));
    float peA = __expf(sA - MA);
    float peB = __expf(sB - MB);
    #pragma unroll
    for (int o = 16; o; o >>= 1) {
        peA += __shfl_xor_sync(0xffffffffu, peA, o);
        peB += __shfl_xor_sync(0xffffffffu, peB, o);
    }
    if (lane == 0) { sm_w3[wid] = peA; sm_w4[wid] = peB; }
    __syncthreads();

    // ---------------- fused deterministic finalization ----------------
    if (tid == 0) {
        const float totA = (sm_w3[0] + sm_w3[1]) + (sm_w3[2] + sm_w3[3]);
        const float totB = (sm_w4[0] + sm_w4[1]) + (sm_w4[2] + sm_w4[3]);
        g_res[b0] = MA + __logf(totA * 0.5f) - pathA;
        g_res[b1] = MB + __logf(totB * 0.5f) - pathB;
        __threadfence();
        sm_last = atomicAdd(&g_done, 1u);     // NCTA-1 for the last CTA
    }
    __syncthreads();
    if (sm_last == NCTA - 1) {
        __threadfence();                      // acquire all g_res
        float acc = (g_res[tid] + g_res[tid + 128])
                  + (g_res[tid + 256] + g_res[tid + 384]);
        #pragma unroll
        for (int o = 16; o; o >>= 1) acc += __shfl_xor_sync(0xffffffffu, acc, o);
        if (lane == 0) sm_w[wid] = acc;
        __syncthreads();
        if (tid == 0) {
            out[0] = ((sm_w[0] + sm_w[1]) + (sm_w[2] + sm_w[3])) * (1.0f / BB);
            g_done = 0;                       // reset for graph replay
        }
    }
}

extern "C" void kernel_launch(void* const* d_in, const int* in_sizes, int n_in,
                              void* d_out, int out_size) {
    const float* emission    = (const float*)d_in[0];
    const int*   target      = (const int*)  d_in[1];
    const float* mask        = (const float*)d_in[2];
    const float* start_trans = (const float*)d_in[3];
    const float* trans       = (const float*)d_in[4];
    const float* end_trans   = (const float*)d_in[5];
    float* out = (float*)d_out;

    crf_main_kernel<<<NCTA, NTHR>>>(emission, target, mask, start_trans, trans,
                                    end_trans, out);
}

// round 10
// speedup vs baseline: 1.5699x; 1.5699x over previous
#include <cuda_runtime.h>
#include <cuda_bf16.h>

#define BB 512
#define TT 512
#define LL 64

__device__ float g_res[BB];
__device__ unsigned int g_done = 0;   // last-CTA ticket (self-resetting)

static __device__ __forceinline__ __nv_bfloat162 asbf2(unsigned int u) {
    return *reinterpret_cast<__nv_bfloat162*>(&u);
}

__global__ void __launch_bounds__(32) crf_main_kernel(
    const float* __restrict__ emission,   // [B,T,L]
    const int*   __restrict__ target,     // [B,T]
    const float* __restrict__ mask,       // [B,T]
    const float* __restrict__ start_trans,// [L]
    const float* __restrict__ trans,      // [L,L]
    const float* __restrict__ end_trans,  // [L]
    float* __restrict__ out)
{
    __shared__ float2 sm_me[TT];                       // (mask, endmask)
    __shared__ __align__(16) unsigned int sm_p[2][LL]; // dup bf16x2 probs
    __shared__ unsigned int sm_last;

    const int b    = blockIdx.x;
    const int lane = threadIdx.x;                // 0..31; labels 2l, 2l+1

    const float*  emb  = emission + (size_t)b * TT * LL;
    const float2* emb2 = (const float2*)emb;     // idx: t*32 + lane
    const int*    tgt  = target   + (size_t)b * TT;
    const float*  mrow = mask     + (size_t)b * TT;

    // stage (mask, end_mask)
    for (int t = lane; t < TT; t += 32) {
        float m  = mrow[t];
        float nm = (t + 1 < TT) ? mrow[t + 1] : 0.0f;
        sm_me[t] = make_float2(m, (m > nm) ? 1.0f : 0.0f);
    }

    // E columns 2l, 2l+1 packed bf16x2: Ep[i] = (E[i][2l], E[i][2l+1])
    __nv_bfloat162 Ep[LL];
    #pragma unroll
    for (int i = 0; i < LL; i++) {
        const float2 tr = ((const float2*)trans)[i * 32 + lane];
        Ep[i] = __floats2bfloat162_rn(__expf(tr.x), __expf(tr.y));
    }
    __syncwarp();

    // ---------------- path score: parallel reduction over t ----------------
    float pacc = 0.0f;
    for (int t = 1 + lane; t < TT; t += 32) {
        const int    tp = tgt[t - 1];
        const int    tc = tgt[t];
        const float2 me = sm_me[t];
        pacc += me.x * (trans[tp * LL + tc] + emb[(size_t)t * LL + tc])
              + me.y * end_trans[tc];
    }
    if (lane == 0) {
        const int t0 = tgt[0];
        pacc += start_trans[t0] + emb[t0];
    }
    #pragma unroll
    for (int o = 16; o; o >>= 1) pacc += __shfl_xor_sync(0xffffffffu, pacc, o);
    const float path_score = pacc;

    // ---------------- forward recursion ----------------
    const float2 st2 = ((const float2*)start_trans)[lane];
    const float2 et2 = ((const float2*)end_trans)[lane];
    const float2 em0 = emb2[lane];
    float sA = st2.x + em0.x;                    // t = 0 scores
    float sB = st2.y + em0.y;

    float S = __shfl_sync(0xffffffffu, sA, 0);   // lagged uniform shift

    float2 em1 = emb2[1 * 32 + lane];            // prefetch distance 2
    float2 em2 = emb2[2 * 32 + lane];

    const __nv_bfloat162 z2 = __float2bfloat162_rn(0.0f);

    for (int t = 1; t < TT; t++) {
        const int    buf    = t & 1;
        const float2 em_cur = em1;
        em1 = em2;
        if (t + 2 < TT) em2 = emb2[(size_t)(t + 2) * 32 + lane];

        // stabilized probs as DUPLICATED bf16x2: sm_p[i] = (p_i, p_i)
        const __nv_bfloat162 dA = __float2bfloat162_rn(__expf(sA - S));
        const __nv_bfloat162 dB = __float2bfloat162_rn(__expf(sB - S));
        uint2 w;
        w.x = *reinterpret_cast<const unsigned int*>(&dA);
        w.y = *reinterpret_cast<const unsigned int*>(&dB);
        ((uint2*)sm_p[buf])[lane] = w;
        __syncwarp();

        // dot for both labels via 64 HFMA2 (bf16x2), 8 chains
        const uint4* q = (const uint4*)sm_p[buf];    // 16 loads of 4 dup-pairs
        __nv_bfloat162 a0 = z2, a1 = z2, a2 = z2, a3 = z2;
        __nv_bfloat162 a4 = z2, a5 = z2, a6 = z2, a7 = z2;
        #pragma unroll
        for (int k = 0; k < 8; k++) {
            const uint4 u = q[2 * k];
            const uint4 v = q[2 * k + 1];
            a0 = __hfma2(asbf2(u.x), Ep[8 * k + 0], a0);
            a1 = __hfma2(asbf2(u.y), Ep[8 * k + 1], a1);
            a2 = __hfma2(asbf2(u.z), Ep[8 * k + 2], a2);
            a3 = __hfma2(asbf2(u.w), Ep[8 * k + 3], a3);
            a4 = __hfma2(asbf2(v.x), Ep[8 * k + 4], a4);
            a5 = __hfma2(asbf2(v.y), Ep[8 * k + 5], a5);
            a6 = __hfma2(asbf2(v.z), Ep[8 * k + 6], a6);
            a7 = __hfma2(asbf2(v.w), Ep[8 * k + 7], a7);
        }
        // fp32 combine tree (removes bf16 rounding of large partials)
        float fa = __low2float(a0),  ga = __high2float(a0);
        float fb = __low2float(a1),  gb = __high2float(a1);
        float fc = __low2float(a2),  gc = __high2float(a2);
        float fd = __low2float(a3),  gd = __high2float(a3);
        fa += __low2float(a4);  ga += __high2float(a4);
        fb += __low2float(a5);  gb += __high2float(a5);
        fc += __low2float(a6);  gc += __high2float(a6);
        fd += __low2float(a7);  gd += __high2float(a7);
        const float dotA = (fa + fb) + (fc + fd);
        const float dotB = (ga + gb) + (gc + gd);

        const float2 me  = sm_me[t];
        const float nxtA = S + __logf(dotA) + em_cur.x;
        const float nxtB = S + __logf(dotB) + em_cur.y;
        sA = me.x * nxtA + (1.0f - me.x) * sA + me.y * et2.x;
        sB = me.x * nxtB + (1.0f - me.x) * sB + me.y * et2.y;

        S = __shfl_sync(0xffffffffu, sA, 0);     // next iteration's shift
    }

    // normalizer = logsumexp over 64 labels (exact, fp32; runs once)
    float wm = fmaxf(sA, sB);
    #pragma unroll
    for (int o = 16; o; o >>= 1) wm = fmaxf(wm, __shfl_xor_sync(0xffffffffu, wm, o));
    float pe = __expf(sA - wm) + __expf(sB - wm);
    #pragma unroll
    for (int o = 16; o; o >>= 1) pe += __shfl_xor_sync(0xffffffffu, pe, o);

    // ---------------- fused deterministic finalization ----------------
    if (lane == 0) {
        const float norm = wm + __logf(pe);
        g_res[b] = norm - path_score;
        __threadfence();
        sm_last = atomicAdd(&g_done, 1u);        // BB-1 for the last CTA
    }
    __syncwarp();
    if (sm_last == BB - 1) {
        __threadfence();                         // acquire all g_res
        float acc = 0.0f;
        #pragma unroll
        for (int k = 0; k < BB / 32; k++) acc += g_res[lane + k * 32];
        #pragma unroll
        for (int o = 16; o; o >>= 1) acc += __shfl_xor_sync(0xffffffffu, acc, o);
        if (lane == 0) {
            out[0] = acc * (1.0f / BB);
            g_done = 0;                          // reset for graph replay
        }
    }
}

extern "C" void kernel_launch(void* const* d_in, const int* in_sizes, int n_in,
                              void* d_out, int out_size) {
    const float* emission    = (const float*)d_in[0];
    const int*   target      = (const int*)  d_in[1];
    const float* mask        = (const float*)d_in[2];
    const float* start_trans = (const float*)d_in[3];
    const float* trans       = (const float*)d_in[4];
    const float* end_trans   = (const float*)d_in[5];
    float* out = (float*)d_out;

    crf_main_kernel<<<BB, 32>>>(emission, target, mask, start_trans, trans,
                                end_trans, out);
}